// round 12
// baseline (speedup 1.0000x reference)
#include <cuda_runtime.h>
#include <cuda_fp16.h>
#include <math.h>
#include <cstdint>

#define CIN   512
#define COUT  256
#define SDIM  512
#define NPS   4480          // per-batch padded pixel stride for Xt (66*66=4356 + slack)
#define NPU   4624          // 68*68 u-grid per (ph,b) plane

// ---------------- device scratch ----------------
__device__ float g_s[8 * CIN];
__device__ float g_wsq[COUT * CIN];
__device__ float g_demod[8 * COUT];
__device__ __align__(16) __half g_xt[(size_t)8 * NPS * CIN];         // 36.7 MB
__device__ __align__(16) __half g_wh[(size_t)9 * CIN * COUT];        // 2.36 MB
__device__ __align__(16) __half g_u[(size_t)4 * 8 * NPU * COUT];     // 75.8 MB

// convT phase taps: gt 0..8  (ph0:4, ph1:2, ph2:2, ph3:1)
__constant__ int c_tapd[9] = {0, 1, 66, 67, 1, 67, 66, 67, 67};
__constant__ int c_wsel[9] = {2*3+2, 2*3+0, 0*3+2, 0*3+0, 2*3+1, 0*3+1, 1*3+2, 1*3+0, 1*3+1};
__constant__ int c_toff[4] = {0, 4, 6, 8};
__constant__ int c_nit[4]  = {64, 32, 32, 16};

// ---------------- PTX helpers ----------------
__device__ __forceinline__ uint32_t smem_u32(const void* p) {
    uint32_t a;
    asm("{ .reg .u64 t; cvta.to.shared.u64 t, %1; cvt.u32.u64 %0, t; }" : "=r"(a) : "l"(p));
    return a;
}
__device__ __forceinline__ void cp16(uint32_t dst, const void* src) {
    asm volatile("cp.async.cg.shared.global [%0], [%1], 16;" :: "r"(dst), "l"(src));
}
#define CP_COMMIT() asm volatile("cp.async.commit_group;" ::: "memory")
#define CP_WAIT(n)  asm volatile("cp.async.wait_group %0;" :: "n"(n) : "memory")

#define LDSM4(r, a) asm volatile( \
    "ldmatrix.sync.aligned.m8n8.x4.shared.b16 {%0,%1,%2,%3},[%4];" \
    : "=r"((r)[0]),"=r"((r)[1]),"=r"((r)[2]),"=r"((r)[3]) : "r"(a))
#define LDSM4T(r, a) asm volatile( \
    "ldmatrix.sync.aligned.m8n8.x4.trans.shared.b16 {%0,%1,%2,%3},[%4];" \
    : "=r"((r)[0]),"=r"((r)[1]),"=r"((r)[2]),"=r"((r)[3]) : "r"(a))
#define MMA16816(d, a, b0, b1) asm volatile( \
    "mma.sync.aligned.m16n8k16.row.col.f32.f16.f16.f32 " \
    "{%0,%1,%2,%3},{%4,%5,%6,%7},{%8,%9},{%0,%1,%2,%3};" \
    : "+f"((d)[0]),"+f"((d)[1]),"+f"((d)[2]),"+f"((d)[3]) \
    : "r"((a)[0]),"r"((a)[1]),"r"((a)[2]),"r"((a)[3]), "r"(b0),"r"(b1))

// ---------------------------------------------------------------------------
// prep1: style (blocks 0..511) | wprep (512..1023) | zero_xtb (1024..1071)
//        | zero_ub (1072..1103).  All mutually independent.
// ---------------------------------------------------------------------------
__global__ void k_prep1(const float* __restrict__ style, const float* __restrict__ mw,
                        const float* __restrict__ mb, const float* __restrict__ weight) {
    const int bx = blockIdx.x, tid = threadIdx.x;
    if (bx < 512) {
        // ---- style: s[b,ci] ----
        int idx = bx * 8 + (tid >> 5);
        int lane = tid & 31;
        int b = idx / CIN, ci = idx - b * CIN;
        const float* st = style + b * SDIM;
        const float* w = mw + ci * SDIM;
        float acc = 0.f;
        for (int d = lane; d < SDIM; d += 32) acc += st[d] * w[d];
#pragma unroll
        for (int o = 16; o; o >>= 1) acc += __shfl_xor_sync(0xffffffffu, acc, o);
        if (lane == 0) g_s[idx] = acc * 0.044194173824159216f + mb[ci];
    } else if (bx < 1024) {
        // ---- wprep: 9 phase-tap weight slices + wsq ----
        int idx = (bx - 512) * 256 + tid;
        int co = idx & 255, ci = idx >> 8;
        float w[9];
        float q = 0.f;
#pragma unroll
        for (int p = 0; p < 9; ++p) {
            w[p] = weight[((size_t)co * CIN + ci) * 9 + p];
            q += w[p] * w[p];
        }
        g_wsq[co * CIN + ci] = q;
#pragma unroll
        for (int gt = 0; gt < 9; ++gt)
            g_wh[((size_t)gt * CIN + ci) * COUT + co] = __float2half(w[c_wsel[gt]]);
    } else if (bx < 1072) {
        // ---- zero Xt border ring + slack rows ----
        int c = bx - 1024;
        int row0 = (c % 6) * 64;
        __half* base = g_xt + (size_t)(c / 6) * NPS * CIN;
        for (int wk = tid; wk < 64 * 64; wk += 256) {
            int row = row0 + (wk >> 6), seg = wk & 63;
            int pp;
            if (row < 66)       pp = row;
            else if (row < 132) pp = 4290 + (row - 66);
            else if (row < 196) pp = (row - 131) * 66;
            else if (row < 260) pp = (row - 195) * 66 + 65;
            else                pp = 4356 + (row - 260);
            ((uint4*)(base + (size_t)pp * CIN))[seg] = make_uint4(0, 0, 0, 0);
        }
    } else {
        // ---- zero u border cells ----
        __half* base = g_u + (size_t)(bx - 1072) * NPU * COUT;
        for (int cell = tid >> 5; cell < 264; cell += 8) {
            int r, X;
            if (cell < 68)       { r = 0;          X = cell; }
            else if (cell < 136) { r = 65;         X = cell - 68; }
            else if (cell < 200) { r = cell - 135; X = 0; }
            else                 { r = cell - 199; X = 65; }
            uint4* p = (uint4*)(base + ((size_t)r * 68 + X) * COUT) + (tid & 31);
            *p = make_uint4(0, 0, 0, 0);
        }
    }
}

// ---------------------------------------------------------------------------
// prep2: xt transpose (blockIdx.y<8) | demod (blockIdx.y==8, blockIdx.x<32)
// grid (64, 9, 8)
// ---------------------------------------------------------------------------
__global__ void k_prep2(const float* __restrict__ x) {
    __shared__ float xs[64][65];
    __shared__ float ss[64];
    const int tid = threadIdx.x;
    if (blockIdx.y < 8) {
        int y = blockIdx.x, ch = blockIdx.y, b = blockIdx.z;
        int ci0 = ch * 64;
        if (tid < 64) ss[tid] = g_s[b * CIN + ci0 + tid];
#pragma unroll
        for (int t = 0; t < 16; ++t) {
            int e = tid + t * 256;
            int ci = e >> 6, xx = e & 63;
            xs[ci][xx] = x[(((size_t)b * CIN + ci0 + ci) * 64 + y) * 64 + xx];
        }
        __syncthreads();
#pragma unroll
        for (int t = 0; t < 4; ++t) {
            int g = tid + t * 256;
            int xx = g >> 4, gl = g & 15;
            __half2 h0 = __floats2half2_rn(xs[gl*4+0][xx] * ss[gl*4+0], xs[gl*4+1][xx] * ss[gl*4+1]);
            __half2 h1 = __floats2half2_rn(xs[gl*4+2][xx] * ss[gl*4+2], xs[gl*4+3][xx] * ss[gl*4+3]);
            size_t pp = (size_t)(y + 1) * 66 + (xx + 1);
            __half2* d = (__half2*)(g_xt + ((size_t)b * NPS + pp) * CIN + ci0 + gl * 4);
            d[0] = h0; d[1] = h1;
        }
    } else if (blockIdx.x < 32) {
        // demod: idx = ((bx*8)+bz)*8 + warp   covers 2048 (b,co) pairs
        int idx = (blockIdx.x * 8 + blockIdx.z) * 8 + (tid >> 5);
        int lane = tid & 31;
        int b = idx / COUT, co = idx - b * COUT;
        float acc = 0.f;
        for (int ci = lane; ci < CIN; ci += 32) {
            float sv = g_s[b * CIN + ci];
            acc += sv * sv * g_wsq[co * CIN + ci];
        }
#pragma unroll
        for (int o = 16; o; o >>= 1) acc += __shfl_xor_sync(0xffffffffu, acc, o);
        if (lane == 0)
            g_demod[idx] = 0.014731391274719738f * rsqrtf(2.1701388888888888e-4f * acc + 1e-8f);
    }
}

// ---------------------------------------------------------------------------
// convT phase GEMM: CTA = 128px x 128co, K = TAPS[ph]*512.  8 warps, 32x64 tiles.
// grid: (34 mtiles, 2 cotiles, 32 = ph*8+b) — ph0 (longest CTAs) first.
// ---------------------------------------------------------------------------
#define A_ROWH   40
#define B_ROWH   136
#define A_BUF    (128 * A_ROWH * 2)
#define B_BUF    (32 * B_ROWH * 2)
#define SMEM_DYN (3 * (A_BUF + B_BUF))

__global__ void __launch_bounds__(256, 2) k_conv1() {
    extern __shared__ __align__(16) char smem[];
    __half* Asm = (__half*)smem;
    __half* Bsm = (__half*)(smem + 3 * A_BUF);

    const int tid = threadIdx.x, lane = tid & 31, wid = tid >> 5;
    const int mtile = blockIdx.x, cotile = blockIdx.y;
    const int ph = blockIdx.z >> 3, b = blockIdx.z & 7;
    const int toff = c_toff[ph], NITER = c_nit[ph];
    const int mwarp = wid & 3, nwarp = wid >> 2;

    const int arow = tid >> 1;
    const int apx = mtile * 128 + arow;
    const __half* aSrc = g_xt + ((size_t)b * NPS + apx) * CIN + (tid & 1) * 16;
    const uint32_t aDst = smem_u32(Asm) + (arow * A_ROWH + (tid & 1) * 16) * 2;

    const __half* bSrc = g_wh + (size_t)(tid >> 3) * COUT + cotile * 128 + (tid & 7) * 8;
    const uint32_t bDst = smem_u32(Bsm) + ((tid >> 3) * B_ROWH + (tid & 7) * 8) * 2;

    const uint32_t aLd = smem_u32(Asm)
        + (((lane & 7) + ((lane >> 3) & 1) * 8 + mwarp * 32) * A_ROWH + (lane >> 4) * 8) * 2;
    const uint32_t bLd = smem_u32(Bsm)
        + ((((lane >> 3) & 1) * 8 + (lane & 7)) * B_ROWH + (lane >> 4) * 8 + nwarp * 64) * 2;

    float d[2][8][4];
#pragma unroll
    for (int i = 0; i < 2; ++i)
#pragma unroll
        for (int j = 0; j < 8; ++j)
#pragma unroll
            for (int k = 0; k < 4; ++k) d[i][j][k] = 0.f;

    auto load = [&](int j, int buf) {
        int gt = toff + (j >> 4), cic = j & 15;
        const __half* as = aSrc + ((ptrdiff_t)c_tapd[gt] << 9) + cic * 32;
        uint32_t ad = aDst + buf * A_BUF;
        cp16(ad, as);
        cp16(ad + 16, as + 8);
        const __half* bs = bSrc + ((size_t)gt * CIN + cic * 32) * COUT;
        uint32_t bd = bDst + buf * B_BUF;
        cp16(bd, bs);
        cp16(bd + 128, bs + 64);
    };

    load(0, 0); CP_COMMIT();
    load(1, 1); CP_COMMIT();

    int buf = 0;
    for (int j = 0; j < NITER; ++j) {
        CP_WAIT(1);
        __syncthreads();
        if (j < NITER - 2) {
            int nbuf = buf + 2; if (nbuf >= 3) nbuf -= 3;
            load(j + 2, nbuf);
            CP_COMMIT();
        }
#pragma unroll
        for (int ks = 0; ks < 2; ++ks) {
            uint32_t a[2][4];
#pragma unroll
            for (int mt = 0; mt < 2; ++mt)
                LDSM4(a[mt], aLd + buf * A_BUF + (mt * 16 * A_ROWH + ks * 16) * 2);
#pragma unroll
            for (int ng = 0; ng < 4; ++ng) {
                uint32_t bb[4];
                LDSM4T(bb, bLd + buf * B_BUF + (ks * 16 * B_ROWH + ng * 16) * 2);
#pragma unroll
                for (int mt = 0; mt < 2; ++mt) {
                    MMA16816(d[mt][ng * 2 + 0], a[mt], bb[0], bb[1]);
                    MMA16816(d[mt][ng * 2 + 1], a[mt], bb[2], bb[3]);
                }
            }
        }
        if (++buf == 3) buf = 0;
    }

    // epilogue: write u fp16 (demod deferred to blur)
    const int r = ph >> 1, c = ph & 1;
#pragma unroll
    for (int mt = 0; mt < 2; ++mt) {
        int pxb = mtile * 128 + mwarp * 32 + mt * 16 + (lane >> 2);
#pragma unroll
        for (int rr = 0; rr < 2; ++rr) {
            int px = pxb + rr * 8;
            int Y = px / 66, X = px - Y * 66;
            if (X > 64 - c || Y > 64 - r) continue;
            __half2* ub = (__half2*)(g_u
                + (((size_t)(ph * 8 + b)) * NPU + (Y + 1) * 68 + (X + 1)) * COUT
                + cotile * 128);
#pragma unroll
            for (int nt = 0; nt < 8; ++nt) {
                int col = nwarp * 64 + nt * 8 + (lane & 3) * 2;
                ub[col >> 1] = __floats2half2_rn(d[mt][nt][rr * 2 + 0], d[mt][nt][rr * 2 + 1]);
            }
        }
    }
}

// ---------------------------------------------------------------------------
// blur: 8 output rows per CTA.  oy = 8t+l.  u rows needed per plane = {4t..4t+5}.
// grid (16 t, 8 cochunk32, 8 b), 256 threads.
// smem su[plane(4)][dr(6)][X(66)][co2(16 half2)], X-stride padded to 17.
// ---------------------------------------------------------------------------
#define SROW   17
#define SPLANE (66 * SROW)
#define BLUR_SMEM (24 * SPLANE * 4)     // 24 plane-rows * 1122 half2 * 4 B = 107712

__global__ void __launch_bounds__(256, 2) k_blur(float* __restrict__ out) {
    extern __shared__ __align__(16) __half2 su[];
    const int tid = threadIdx.x;
    const int t = blockIdx.x, cochunk = blockIdx.y, b = blockIdx.z;
    const int cobase = cochunk * 32;
    const int co2 = tid & 15, oxg = tid >> 4;   // 16 co-half2 lanes, 16 ox-groups of 8

    // load 4 planes x 6 rows (4t..4t+5) x 66 X x 16 half2 = 25344 elements (99 iters exact)
    for (int e = tid; e < 25344; e += 256) {
        int cc = e & 15, rest = e >> 4;
        int X = rest % 66, pr = rest / 66;       // pr = plane*6+dr
        int plane = pr / 6, dr = pr - plane * 6;
        const __half2* src = (const __half2*)(g_u
            + (((size_t)(plane * 8 + b)) * NPU + (size_t)(4 * t + dr) * 68 + X) * COUT
            + cobase) + cc;
        su[(size_t)pr * SPLANE + X * SROW + cc] = *src;
    }
    __syncthreads();

    const float kv[4] = {0.25f, 0.75f, 0.75f, 0.25f};
    const int co = cobase + co2 * 2;
    const float dm0 = g_demod[b * 256 + co];
    const float dm1 = g_demod[b * 256 + co + 1];

#pragma unroll
    for (int l = 0; l < 8; ++l) {
        const int u0 = 8 * t + l - 1;
        const int r0 = u0 & 1;
        int lrow[2][2]; float kva[2][2];
#pragma unroll
        for (int p = 0; p < 2; ++p) {
            int a0 = (p == r0) ? 0 : 1;
#pragma unroll
            for (int s = 0; s < 2; ++s) {
                lrow[p][s] = ((u0 + a0) >> 1) + s + 1 - 4 * t;   // 0..5
                kva[p][s] = kv[a0 + 2 * s];
            }
        }
        float ax[8], ay[8];
#pragma unroll
        for (int i = 0; i < 8; ++i) {
            int ox = oxg * 8 + i;
            int ux0 = ox - 1, c0 = ux0 & 1;
            float sx = 0.f, sy = 0.f;
#pragma unroll
            for (int cp = 0; cp < 2; ++cp) {
                int b0 = (cp == c0) ? 0 : 1;
                int Xb = ((ux0 + b0) >> 1) + 1;
#pragma unroll
                for (int tt = 0; tt < 2; ++tt) {
                    float kvb = kv[b0 + 2 * tt];
#pragma unroll
                    for (int p = 0; p < 2; ++p)
#pragma unroll
                        for (int s = 0; s < 2; ++s) {
                            float w = kva[p][s] * kvb;
                            __half2 v = su[(size_t)((p * 2 + cp) * 6 + lrow[p][s]) * SPLANE
                                           + (Xb + tt) * SROW + co2];
                            float2 vf = __half22float2(v);
                            sx += w * vf.x;
                            sy += w * vf.y;
                        }
                }
            }
            ax[i] = sx * dm0;
            ay[i] = sy * dm1;
        }
        const int oy = 8 * t + l;
        float* ob0 = out + (((size_t)b * 256 + co) * 128 + oy) * 128 + oxg * 8;
        float* ob1 = ob0 + 16384;
        ((float4*)ob0)[0] = make_float4(ax[0], ax[1], ax[2], ax[3]);
        ((float4*)ob0)[1] = make_float4(ax[4], ax[5], ax[6], ax[7]);
        ((float4*)ob1)[0] = make_float4(ay[0], ay[1], ay[2], ay[3]);
        ((float4*)ob1)[1] = make_float4(ay[4], ay[5], ay[6], ay[7]);
    }
}

// ---------------------------------------------------------------------------
extern "C" void kernel_launch(void* const* d_in, const int* in_sizes, int n_in,
                              void* d_out, int out_size) {
    const float* x          = (const float*)d_in[0];
    const float* style      = (const float*)d_in[1];
    const float* weight     = (const float*)d_in[2];
    const float* mod_weight = (const float*)d_in[3];
    const float* mod_bias   = (const float*)d_in[4];
    float* out = (float*)d_out;

    static int smem_set = 0;
    if (!smem_set) {
        cudaFuncSetAttribute(k_conv1, cudaFuncAttributeMaxDynamicSharedMemorySize, SMEM_DYN);
        cudaFuncSetAttribute(k_blur, cudaFuncAttributeMaxDynamicSharedMemorySize, BLUR_SMEM);
        smem_set = 1;
    }

    k_prep1<<<1104, 256>>>(style, mod_weight, mod_bias, weight);
    k_prep2<<<dim3(64, 9, 8), 256>>>(x);
    k_conv1<<<dim3(34, 2, 32), 256, SMEM_DYN>>>();
    k_blur<<<dim3(16, 8, 8), 256, BLUR_SMEM>>>(out);
}

// round 14
// speedup vs baseline: 1.0210x; 1.0210x over previous
#include <cuda_runtime.h>
#include <cuda_fp16.h>
#include <math.h>
#include <cstdint>

#define CIN   512
#define COUT  256
#define SDIM  512
#define NPS   4480          // per-batch padded pixel stride for Xt (66*66=4356 + slack)
#define NPU   4624          // 68*68 u-grid per (ph,b) plane

// ---------------- device scratch ----------------
__device__ float g_s[8 * CIN];
__device__ float g_wsq[COUT * CIN];
__device__ float g_demod[8 * COUT];
__device__ __align__(16) __half g_xt[(size_t)8 * NPS * CIN];         // 36.7 MB
__device__ __align__(16) __half g_wh[(size_t)9 * CIN * COUT];        // 2.36 MB
__device__ __align__(16) __half g_u[(size_t)4 * 8 * NPU * COUT];     // 75.8 MB

// convT phase taps: gt 0..8  (ph0:4, ph1:2, ph2:2, ph3:1)
__constant__ int c_tapd[9] = {0, 1, 66, 67, 1, 67, 66, 67, 67};
__constant__ int c_wsel[9] = {2*3+2, 2*3+0, 0*3+2, 0*3+0, 2*3+1, 0*3+1, 1*3+2, 1*3+0, 1*3+1};
__constant__ int c_toff[4] = {0, 4, 6, 8};
__constant__ int c_nit[4]  = {64, 32, 32, 16};

// ---------------- PTX helpers ----------------
__device__ __forceinline__ uint32_t smem_u32(const void* p) {
    uint32_t a;
    asm("{ .reg .u64 t; cvta.to.shared.u64 t, %1; cvt.u32.u64 %0, t; }" : "=r"(a) : "l"(p));
    return a;
}
__device__ __forceinline__ void cp16(uint32_t dst, const void* src) {
    asm volatile("cp.async.cg.shared.global [%0], [%1], 16;" :: "r"(dst), "l"(src));
}
#define CP_COMMIT() asm volatile("cp.async.commit_group;" ::: "memory")
#define CP_WAIT(n)  asm volatile("cp.async.wait_group %0;" :: "n"(n) : "memory")

#define LDSM4(r, a) asm volatile( \
    "ldmatrix.sync.aligned.m8n8.x4.shared.b16 {%0,%1,%2,%3},[%4];" \
    : "=r"((r)[0]),"=r"((r)[1]),"=r"((r)[2]),"=r"((r)[3]) : "r"(a))
#define LDSM4T(r, a) asm volatile( \
    "ldmatrix.sync.aligned.m8n8.x4.trans.shared.b16 {%0,%1,%2,%3},[%4];" \
    : "=r"((r)[0]),"=r"((r)[1]),"=r"((r)[2]),"=r"((r)[3]) : "r"(a))
#define MMA16816(d, a, b0, b1) asm volatile( \
    "mma.sync.aligned.m16n8k16.row.col.f32.f16.f16.f32 " \
    "{%0,%1,%2,%3},{%4,%5,%6,%7},{%8,%9},{%0,%1,%2,%3};" \
    : "+f"((d)[0]),"+f"((d)[1]),"+f"((d)[2]),"+f"((d)[3]) \
    : "r"((a)[0]),"r"((a)[1]),"r"((a)[2]),"r"((a)[3]), "r"(b0),"r"(b1))

// ---------------------------------------------------------------------------
__global__ void k_style(const float* __restrict__ style, const float* __restrict__ mw,
                        const float* __restrict__ mb) {
    int idx = blockIdx.x * 8 + (threadIdx.x >> 5);
    int lane = threadIdx.x & 31;
    int b = idx / CIN, ci = idx - b * CIN;
    const float* st = style + b * SDIM;
    const float* w = mw + ci * SDIM;
    float acc = 0.f;
    for (int d = lane; d < SDIM; d += 32) acc += st[d] * w[d];
#pragma unroll
    for (int o = 16; o; o >>= 1) acc += __shfl_xor_sync(0xffffffffu, acc, o);
    if (lane == 0) g_s[idx] = acc * 0.044194173824159216f + mb[ci];
}

// zero ONLY Xt rows never written by k_xt: border ring of 66x66 + slack rows.
__global__ void k_zero_xtb() {
    __half* base = g_xt + (size_t)blockIdx.y * NPS * CIN;
    int row0 = blockIdx.x * 64;
    for (int w = threadIdx.x; w < 64 * 64; w += 256) {
        int row = row0 + (w >> 6), seg = w & 63;
        int pp;
        if (row < 66)       pp = row;
        else if (row < 132) pp = 4290 + (row - 66);
        else if (row < 196) pp = (row - 131) * 66;
        else if (row < 260) pp = (row - 195) * 66 + 65;
        else                pp = 4356 + (row - 260);
        ((uint4*)(base + (size_t)pp * CIN))[seg] = make_uint4(0, 0, 0, 0);
    }
}

// zero u border cells read by blur but never written by conv1
__global__ void k_zero_ub() {
    __half* base = g_u + (size_t)blockIdx.x * NPU * COUT;
    int tid = threadIdx.x;
    for (int cell = tid >> 5; cell < 264; cell += 8) {
        int r, X;
        if (cell < 68)       { r = 0;          X = cell; }
        else if (cell < 136) { r = 65;         X = cell - 68; }
        else if (cell < 200) { r = cell - 135; X = 0; }
        else                 { r = cell - 199; X = 65; }
        uint4* p = (uint4*)(base + ((size_t)r * 68 + X) * COUT) + (tid & 31);
        *p = make_uint4(0, 0, 0, 0);
    }
}

// transpose + modulate + fp16: Xt[b][(y+1)*66+(x+1)][ci]
__global__ void k_xt(const float* __restrict__ x) {
    __shared__ float xs[64][65];
    __shared__ float ss[64];
    int y = blockIdx.x, ch = blockIdx.y, b = blockIdx.z;
    int ci0 = ch * 64, tid = threadIdx.x;
    if (tid < 64) ss[tid] = g_s[b * CIN + ci0 + tid];
#pragma unroll
    for (int t = 0; t < 16; ++t) {
        int e = tid + t * 256;
        int ci = e >> 6, xx = e & 63;
        xs[ci][xx] = x[(((size_t)b * CIN + ci0 + ci) * 64 + y) * 64 + xx];
    }
    __syncthreads();
#pragma unroll
    for (int t = 0; t < 4; ++t) {
        int g = tid + t * 256;
        int xx = g >> 4, gl = g & 15;
        __half2 h0 = __floats2half2_rn(xs[gl*4+0][xx] * ss[gl*4+0], xs[gl*4+1][xx] * ss[gl*4+1]);
        __half2 h1 = __floats2half2_rn(xs[gl*4+2][xx] * ss[gl*4+2], xs[gl*4+3][xx] * ss[gl*4+3]);
        size_t pp = (size_t)(y + 1) * 66 + (xx + 1);
        __half2* d = (__half2*)(g_xt + ((size_t)b * NPS + pp) * CIN + ci0 + gl * 4);
        d[0] = h0; d[1] = h1;
    }
}

// raw conv weights -> 9 phase-tap slices [gt][ci][co], + wsq
__global__ void k_wprep(const float* __restrict__ weight) {
    int idx = blockIdx.x * 256 + threadIdx.x;     // 131072
    int co = idx & 255, ci = idx >> 8;
    float w[9];
    float q = 0.f;
#pragma unroll
    for (int p = 0; p < 9; ++p) {
        w[p] = weight[((size_t)co * CIN + ci) * 9 + p];
        q += w[p] * w[p];
    }
    g_wsq[co * CIN + ci] = q;
#pragma unroll
    for (int gt = 0; gt < 9; ++gt)
        g_wh[((size_t)gt * CIN + ci) * COUT + co] = __float2half(w[c_wsel[gt]]);
}

__global__ void k_demod() {
    int idx = blockIdx.x * 8 + (threadIdx.x >> 5);
    int lane = threadIdx.x & 31;
    int b = idx / COUT, co = idx - b * COUT;
    float acc = 0.f;
    for (int ci = lane; ci < CIN; ci += 32) {
        float sv = g_s[b * CIN + ci];
        acc += sv * sv * g_wsq[co * CIN + ci];
    }
#pragma unroll
    for (int o = 16; o; o >>= 1) acc += __shfl_xor_sync(0xffffffffu, acc, o);
    if (lane == 0)
        g_demod[idx] = 0.014731391274719738f * rsqrtf(2.1701388888888888e-4f * acc + 1e-8f);
}

// ---------------------------------------------------------------------------
// convT phase GEMM: CTA = 128px x 128co, K = TAPS[ph]*512.  8 warps, 32x64 tiles.
// grid: (34 mtiles, 2 cotiles, 32 = ph*8+b) — ph0 (longest CTAs) first.
// ---------------------------------------------------------------------------
#define A_ROWH   40
#define B_ROWH   136
#define A_BUF    (128 * A_ROWH * 2)
#define B_BUF    (32 * B_ROWH * 2)
#define SMEM_DYN (3 * (A_BUF + B_BUF))

__global__ void __launch_bounds__(256, 2) k_conv1() {
    extern __shared__ __align__(16) char smem[];
    __half* Asm = (__half*)smem;
    __half* Bsm = (__half*)(smem + 3 * A_BUF);

    const int tid = threadIdx.x, lane = tid & 31, wid = tid >> 5;
    const int mtile = blockIdx.x, cotile = blockIdx.y;
    const int ph = blockIdx.z >> 3, b = blockIdx.z & 7;
    const int toff = c_toff[ph], NITER = c_nit[ph];
    const int mwarp = wid & 3, nwarp = wid >> 2;

    const int arow = tid >> 1;
    const int apx = mtile * 128 + arow;
    const __half* aSrc = g_xt + ((size_t)b * NPS + apx) * CIN + (tid & 1) * 16;
    const uint32_t aDst = smem_u32(Asm) + (arow * A_ROWH + (tid & 1) * 16) * 2;

    const __half* bSrc = g_wh + (size_t)(tid >> 3) * COUT + cotile * 128 + (tid & 7) * 8;
    const uint32_t bDst = smem_u32(Bsm) + ((tid >> 3) * B_ROWH + (tid & 7) * 8) * 2;

    const uint32_t aLd = smem_u32(Asm)
        + (((lane & 7) + ((lane >> 3) & 1) * 8 + mwarp * 32) * A_ROWH + (lane >> 4) * 8) * 2;
    const uint32_t bLd = smem_u32(Bsm)
        + ((((lane >> 3) & 1) * 8 + (lane & 7)) * B_ROWH + (lane >> 4) * 8 + nwarp * 64) * 2;

    float d[2][8][4];
#pragma unroll
    for (int i = 0; i < 2; ++i)
#pragma unroll
        for (int j = 0; j < 8; ++j)
#pragma unroll
            for (int k = 0; k < 4; ++k) d[i][j][k] = 0.f;

    auto load = [&](int j, int buf) {
        int gt = toff + (j >> 4), cic = j & 15;
        const __half* as = aSrc + ((ptrdiff_t)c_tapd[gt] << 9) + cic * 32;
        uint32_t ad = aDst + buf * A_BUF;
        cp16(ad, as);
        cp16(ad + 16, as + 8);
        const __half* bs = bSrc + ((size_t)gt * CIN + cic * 32) * COUT;
        uint32_t bd = bDst + buf * B_BUF;
        cp16(bd, bs);
        cp16(bd + 128, bs + 64);
    };

    load(0, 0); CP_COMMIT();
    load(1, 1); CP_COMMIT();

    int buf = 0;
    for (int j = 0; j < NITER; ++j) {
        CP_WAIT(1);
        __syncthreads();
        if (j < NITER - 2) {
            int nbuf = buf + 2; if (nbuf >= 3) nbuf -= 3;
            load(j + 2, nbuf);
            CP_COMMIT();
        }
#pragma unroll
        for (int ks = 0; ks < 2; ++ks) {
            uint32_t a[2][4];
#pragma unroll
            for (int mt = 0; mt < 2; ++mt)
                LDSM4(a[mt], aLd + buf * A_BUF + (mt * 16 * A_ROWH + ks * 16) * 2);
#pragma unroll
            for (int ng = 0; ng < 4; ++ng) {
                uint32_t bb[4];
                LDSM4T(bb, bLd + buf * B_BUF + (ks * 16 * B_ROWH + ng * 16) * 2);
#pragma unroll
                for (int mt = 0; mt < 2; ++mt) {
                    MMA16816(d[mt][ng * 2 + 0], a[mt], bb[0], bb[1]);
                    MMA16816(d[mt][ng * 2 + 1], a[mt], bb[2], bb[3]);
                }
            }
        }
        if (++buf == 3) buf = 0;
    }

    const int r = ph >> 1, c = ph & 1;
#pragma unroll
    for (int mt = 0; mt < 2; ++mt) {
        int pxb = mtile * 128 + mwarp * 32 + mt * 16 + (lane >> 2);
#pragma unroll
        for (int rr = 0; rr < 2; ++rr) {
            int px = pxb + rr * 8;
            int Y = px / 66, X = px - Y * 66;
            if (X > 64 - c || Y > 64 - r) continue;
            __half2* ub = (__half2*)(g_u
                + (((size_t)(ph * 8 + b)) * NPU + (Y + 1) * 68 + (X + 1)) * COUT
                + cotile * 128);
#pragma unroll
            for (int nt = 0; nt < 8; ++nt) {
                int col = nwarp * 64 + nt * 8 + (lane & 3) * 2;
                ub[col >> 1] = __floats2half2_rn(d[mt][nt][rr * 2 + 0], d[mt][nt][rr * 2 + 1]);
            }
        }
    }
}

// ---------------------------------------------------------------------------
// blur: 4 output rows per CTA (round-11 math verbatim; only occupancy bound changed).
// grid (32 t, 8 cochunk32, 8 b), 256 threads.
// ---------------------------------------------------------------------------
#define SROW   17
#define SPLANE (66 * SROW)
#define BLUR_SMEM (16 * SPLANE * 4)     // 71808 B

__global__ void __launch_bounds__(256, 3) k_blur(float* __restrict__ out) {
    extern __shared__ __align__(16) __half2 su[];
    const int tid = threadIdx.x;
    const int t = blockIdx.x, cochunk = blockIdx.y, b = blockIdx.z;
    const int cobase = cochunk * 32;
    const int co2 = tid & 15, oxg = tid >> 4;

    // load 4 planes x 4 rows (2t..2t+3) x 66 X x 16 half2
    for (int it = 0; it < 66; ++it) {
        int e = tid + it * 256;
        int cc = e & 15, rest = e >> 4;
        int X = rest % 66, pr = rest / 66;       // pr = plane*4+dr
        const __half2* src = (const __half2*)(g_u
            + (((size_t)((pr >> 2) * 8 + b)) * NPU + (size_t)(2 * t + (pr & 3)) * 68 + X) * COUT
            + cobase) + cc;
        su[(size_t)pr * SPLANE + X * SROW + cc] = *src;
    }
    __syncthreads();

    const float kv[4] = {0.25f, 0.75f, 0.75f, 0.25f};
    const int co = cobase + co2 * 2;
    const float dm0 = g_demod[b * 256 + co];
    const float dm1 = g_demod[b * 256 + co + 1];

#pragma unroll
    for (int l = 0; l < 4; ++l) {
        const int u0 = 4 * t + l - 1;
        const int r0 = u0 & 1;
        int lrow[2][2]; float kva[2][2];
#pragma unroll
        for (int p = 0; p < 2; ++p) {
            int a0 = (p == r0) ? 0 : 1;
#pragma unroll
            for (int s = 0; s < 2; ++s) {
                lrow[p][s] = ((u0 + a0) >> 1) + s + 1 - 2 * t;   // 0..3
                kva[p][s] = kv[a0 + 2 * s];
            }
        }
        float ax[8], ay[8];
#pragma unroll
        for (int i = 0; i < 8; ++i) {
            int ox = oxg * 8 + i;
            int ux0 = ox - 1, c0 = ux0 & 1;
            float sx = 0.f, sy = 0.f;
#pragma unroll
            for (int cp = 0; cp < 2; ++cp) {
                int b0 = (cp == c0) ? 0 : 1;
                int Xb = ((ux0 + b0) >> 1) + 1;
#pragma unroll
                for (int tt = 0; tt < 2; ++tt) {
                    float kvb = kv[b0 + 2 * tt];
#pragma unroll
                    for (int p = 0; p < 2; ++p)
#pragma unroll
                        for (int s = 0; s < 2; ++s) {
                            float w = kva[p][s] * kvb;
                            __half2 v = su[(size_t)((p * 2 + cp) * 4 + lrow[p][s]) * SPLANE
                                           + (Xb + tt) * SROW + co2];
                            float2 vf = __half22float2(v);
                            sx += w * vf.x;
                            sy += w * vf.y;
                        }
                }
            }
            ax[i] = sx * dm0;
            ay[i] = sy * dm1;
        }
        const int oy = 4 * t + l;
        float* ob0 = out + (((size_t)b * 256 + co) * 128 + oy) * 128 + oxg * 8;
        float* ob1 = ob0 + 16384;
        ((float4*)ob0)[0] = make_float4(ax[0], ax[1], ax[2], ax[3]);
        ((float4*)ob0)[1] = make_float4(ax[4], ax[5], ax[6], ax[7]);
        ((float4*)ob1)[0] = make_float4(ay[0], ay[1], ay[2], ay[3]);
        ((float4*)ob1)[1] = make_float4(ay[4], ay[5], ay[6], ay[7]);
    }
}

// ---------------------------------------------------------------------------
extern "C" void kernel_launch(void* const* d_in, const int* in_sizes, int n_in,
                              void* d_out, int out_size) {
    const float* x          = (const float*)d_in[0];
    const float* style      = (const float*)d_in[1];
    const float* weight     = (const float*)d_in[2];
    const float* mod_weight = (const float*)d_in[3];
    const float* mod_bias   = (const float*)d_in[4];
    float* out = (float*)d_out;

    static int smem_set = 0;
    if (!smem_set) {
        cudaFuncSetAttribute(k_conv1, cudaFuncAttributeMaxDynamicSharedMemorySize, SMEM_DYN);
        cudaFuncSetAttribute(k_blur, cudaFuncAttributeMaxDynamicSharedMemorySize, BLUR_SMEM);
        smem_set = 1;
    }

    k_style<<<512, 256>>>(style, mod_weight, mod_bias);
    k_zero_xtb<<<dim3(6, 8), 256>>>();
    k_zero_ub<<<32, 256>>>();
    k_xt<<<dim3(64, 8, 8), 256>>>(x);
    k_wprep<<<512, 256>>>(weight);
    k_demod<<<256, 256>>>();
    k_conv1<<<dim3(34, 2, 32), 256, SMEM_DYN>>>();
    k_blur<<<dim3(32, 8, 8), 256, BLUR_SMEM>>>(out);
}

// round 15
// speedup vs baseline: 1.0558x; 1.0341x over previous
#include <cuda_runtime.h>
#include <cuda_fp16.h>
#include <math.h>
#include <cstdint>

#define CIN   512
#define COUT  256
#define SDIM  512
#define NPS   4480          // per-batch padded pixel stride for Xt (66*66=4356 + slack)
#define NPU   4624          // 68*68 u-grid per (ph,b) plane

// ---------------- device scratch ----------------
__device__ float g_s[8 * CIN];
__device__ float g_wsq[COUT * CIN];
__device__ float g_demod[8 * COUT];
__device__ __align__(16) __half g_xt[(size_t)8 * NPS * CIN];         // 36.7 MB
__device__ __align__(16) __half g_wh[(size_t)9 * CIN * COUT];        // 2.36 MB
__device__ __align__(16) __half g_u[(size_t)4 * 8 * NPU * COUT];     // 75.8 MB

// convT phase taps: gt 0..8  (ph0:4, ph1:2, ph2:2, ph3:1)
__constant__ int c_tapd[9] = {0, 1, 66, 67, 1, 67, 66, 67, 67};
__constant__ int c_wsel[9] = {2*3+2, 2*3+0, 0*3+2, 0*3+0, 2*3+1, 0*3+1, 1*3+2, 1*3+0, 1*3+1};
__constant__ int c_toff[4] = {0, 4, 6, 8};
__constant__ int c_nit[4]  = {64, 32, 32, 16};

// ---------------- PTX helpers ----------------
__device__ __forceinline__ uint32_t smem_u32(const void* p) {
    uint32_t a;
    asm("{ .reg .u64 t; cvta.to.shared.u64 t, %1; cvt.u32.u64 %0, t; }" : "=r"(a) : "l"(p));
    return a;
}
__device__ __forceinline__ void cp16(uint32_t dst, const void* src) {
    asm volatile("cp.async.cg.shared.global [%0], [%1], 16;" :: "r"(dst), "l"(src));
}
#define CP_COMMIT() asm volatile("cp.async.commit_group;" ::: "memory")
#define CP_WAIT(n)  asm volatile("cp.async.wait_group %0;" :: "n"(n) : "memory")

#define LDSM4(r, a) asm volatile( \
    "ldmatrix.sync.aligned.m8n8.x4.shared.b16 {%0,%1,%2,%3},[%4];" \
    : "=r"((r)[0]),"=r"((r)[1]),"=r"((r)[2]),"=r"((r)[3]) : "r"(a))
#define LDSM4T(r, a) asm volatile( \
    "ldmatrix.sync.aligned.m8n8.x4.trans.shared.b16 {%0,%1,%2,%3},[%4];" \
    : "=r"((r)[0]),"=r"((r)[1]),"=r"((r)[2]),"=r"((r)[3]) : "r"(a))
#define MMA16816(d, a, b0, b1) asm volatile( \
    "mma.sync.aligned.m16n8k16.row.col.f32.f16.f16.f32 " \
    "{%0,%1,%2,%3},{%4,%5,%6,%7},{%8,%9},{%0,%1,%2,%3};" \
    : "+f"((d)[0]),"+f"((d)[1]),"+f"((d)[2]),"+f"((d)[3]) \
    : "r"((a)[0]),"r"((a)[1]),"r"((a)[2]),"r"((a)[3]), "r"(b0),"r"(b1))

// ---------------------------------------------------------------------------
// prep1: style (blocks 0..511) | wprep (512..1023) | zero_xtb (1024..1071)
//        | zero_ub (1072..1103).  All mutually independent.
// ---------------------------------------------------------------------------
__global__ void k_prep1(const float* __restrict__ style, const float* __restrict__ mw,
                        const float* __restrict__ mb, const float* __restrict__ weight) {
    const int bx = blockIdx.x, tid = threadIdx.x;
    if (bx < 512) {
        int idx = bx * 8 + (tid >> 5);
        int lane = tid & 31;
        int b = idx / CIN, ci = idx - b * CIN;
        const float* st = style + b * SDIM;
        const float* w = mw + ci * SDIM;
        float acc = 0.f;
        for (int d = lane; d < SDIM; d += 32) acc += st[d] * w[d];
#pragma unroll
        for (int o = 16; o; o >>= 1) acc += __shfl_xor_sync(0xffffffffu, acc, o);
        if (lane == 0) g_s[idx] = acc * 0.044194173824159216f + mb[ci];
    } else if (bx < 1024) {
        int idx = (bx - 512) * 256 + tid;
        int co = idx & 255, ci = idx >> 8;
        float w[9];
        float q = 0.f;
#pragma unroll
        for (int p = 0; p < 9; ++p) {
            w[p] = weight[((size_t)co * CIN + ci) * 9 + p];
            q += w[p] * w[p];
        }
        g_wsq[co * CIN + ci] = q;
#pragma unroll
        for (int gt = 0; gt < 9; ++gt)
            g_wh[((size_t)gt * CIN + ci) * COUT + co] = __float2half(w[c_wsel[gt]]);
    } else if (bx < 1072) {
        int c = bx - 1024;
        int row0 = (c % 6) * 64;
        __half* base = g_xt + (size_t)(c / 6) * NPS * CIN;
        for (int wk = tid; wk < 64 * 64; wk += 256) {
            int row = row0 + (wk >> 6), seg = wk & 63;
            int pp;
            if (row < 66)       pp = row;
            else if (row < 132) pp = 4290 + (row - 66);
            else if (row < 196) pp = (row - 131) * 66;
            else if (row < 260) pp = (row - 195) * 66 + 65;
            else                pp = 4356 + (row - 260);
            ((uint4*)(base + (size_t)pp * CIN))[seg] = make_uint4(0, 0, 0, 0);
        }
    } else {
        __half* base = g_u + (size_t)(bx - 1072) * NPU * COUT;
        for (int cell = tid >> 5; cell < 264; cell += 8) {
            int r, X;
            if (cell < 68)       { r = 0;          X = cell; }
            else if (cell < 136) { r = 65;         X = cell - 68; }
            else if (cell < 200) { r = cell - 135; X = 0; }
            else                 { r = cell - 199; X = 65; }
            uint4* p = (uint4*)(base + ((size_t)r * 68 + X) * COUT) + (tid & 31);
            *p = make_uint4(0, 0, 0, 0);
        }
    }
}

// ---------------------------------------------------------------------------
// prep2: xt transpose (blockIdx.y<8) | demod (blockIdx.y==8, blockIdx.x<32)
// grid (64, 9, 8)
// ---------------------------------------------------------------------------
__global__ void k_prep2(const float* __restrict__ x) {
    __shared__ float xs[64][65];
    __shared__ float ss[64];
    const int tid = threadIdx.x;
    if (blockIdx.y < 8) {
        int y = blockIdx.x, ch = blockIdx.y, b = blockIdx.z;
        int ci0 = ch * 64;
        if (tid < 64) ss[tid] = g_s[b * CIN + ci0 + tid];
#pragma unroll
        for (int t = 0; t < 16; ++t) {
            int e = tid + t * 256;
            int ci = e >> 6, xx = e & 63;
            xs[ci][xx] = x[(((size_t)b * CIN + ci0 + ci) * 64 + y) * 64 + xx];
        }
        __syncthreads();
#pragma unroll
        for (int t = 0; t < 4; ++t) {
            int g = tid + t * 256;
            int xx = g >> 4, gl = g & 15;
            __half2 h0 = __floats2half2_rn(xs[gl*4+0][xx] * ss[gl*4+0], xs[gl*4+1][xx] * ss[gl*4+1]);
            __half2 h1 = __floats2half2_rn(xs[gl*4+2][xx] * ss[gl*4+2], xs[gl*4+3][xx] * ss[gl*4+3]);
            size_t pp = (size_t)(y + 1) * 66 + (xx + 1);
            __half2* d = (__half2*)(g_xt + ((size_t)b * NPS + pp) * CIN + ci0 + gl * 4);
            d[0] = h0; d[1] = h1;
        }
    } else if (blockIdx.x < 32) {
        int idx = (blockIdx.x * 8 + blockIdx.z) * 8 + (tid >> 5);
        int lane = tid & 31;
        int b = idx / COUT, co = idx - b * COUT;
        float acc = 0.f;
        for (int ci = lane; ci < CIN; ci += 32) {
            float sv = g_s[b * CIN + ci];
            acc += sv * sv * g_wsq[co * CIN + ci];
        }
#pragma unroll
        for (int o = 16; o; o >>= 1) acc += __shfl_xor_sync(0xffffffffu, acc, o);
        if (lane == 0)
            g_demod[idx] = 0.014731391274719738f * rsqrtf(2.1701388888888888e-4f * acc + 1e-8f);
    }
}

// ---------------------------------------------------------------------------
// convT phase GEMM (unchanged): CTA = 128px x 128co, 8 warps, 32x64 tiles.
// grid: (34 mtiles, 2 cotiles, 32 = ph*8+b) — ph0 (longest CTAs) first.
// ---------------------------------------------------------------------------
#define A_ROWH   40
#define B_ROWH   136
#define A_BUF    (128 * A_ROWH * 2)
#define B_BUF    (32 * B_ROWH * 2)
#define SMEM_DYN (3 * (A_BUF + B_BUF))

__global__ void __launch_bounds__(256, 2) k_conv1() {
    extern __shared__ __align__(16) char smem[];
    __half* Asm = (__half*)smem;
    __half* Bsm = (__half*)(smem + 3 * A_BUF);

    const int tid = threadIdx.x, lane = tid & 31, wid = tid >> 5;
    const int mtile = blockIdx.x, cotile = blockIdx.y;
    const int ph = blockIdx.z >> 3, b = blockIdx.z & 7;
    const int toff = c_toff[ph], NITER = c_nit[ph];
    const int mwarp = wid & 3, nwarp = wid >> 2;

    const int arow = tid >> 1;
    const int apx = mtile * 128 + arow;
    const __half* aSrc = g_xt + ((size_t)b * NPS + apx) * CIN + (tid & 1) * 16;
    const uint32_t aDst = smem_u32(Asm) + (arow * A_ROWH + (tid & 1) * 16) * 2;

    const __half* bSrc = g_wh + (size_t)(tid >> 3) * COUT + cotile * 128 + (tid & 7) * 8;
    const uint32_t bDst = smem_u32(Bsm) + ((tid >> 3) * B_ROWH + (tid & 7) * 8) * 2;

    const uint32_t aLd = smem_u32(Asm)
        + (((lane & 7) + ((lane >> 3) & 1) * 8 + mwarp * 32) * A_ROWH + (lane >> 4) * 8) * 2;
    const uint32_t bLd = smem_u32(Bsm)
        + ((((lane >> 3) & 1) * 8 + (lane & 7)) * B_ROWH + (lane >> 4) * 8 + nwarp * 64) * 2;

    float d[2][8][4];
#pragma unroll
    for (int i = 0; i < 2; ++i)
#pragma unroll
        for (int j = 0; j < 8; ++j)
#pragma unroll
            for (int k = 0; k < 4; ++k) d[i][j][k] = 0.f;

    auto load = [&](int j, int buf) {
        int gt = toff + (j >> 4), cic = j & 15;
        const __half* as = aSrc + ((ptrdiff_t)c_tapd[gt] << 9) + cic * 32;
        uint32_t ad = aDst + buf * A_BUF;
        cp16(ad, as);
        cp16(ad + 16, as + 8);
        const __half* bs = bSrc + ((size_t)gt * CIN + cic * 32) * COUT;
        uint32_t bd = bDst + buf * B_BUF;
        cp16(bd, bs);
        cp16(bd + 128, bs + 64);
    };

    load(0, 0); CP_COMMIT();
    load(1, 1); CP_COMMIT();

    int buf = 0;
    for (int j = 0; j < NITER; ++j) {
        CP_WAIT(1);
        __syncthreads();
        if (j < NITER - 2) {
            int nbuf = buf + 2; if (nbuf >= 3) nbuf -= 3;
            load(j + 2, nbuf);
            CP_COMMIT();
        }
#pragma unroll
        for (int ks = 0; ks < 2; ++ks) {
            uint32_t a[2][4];
#pragma unroll
            for (int mt = 0; mt < 2; ++mt)
                LDSM4(a[mt], aLd + buf * A_BUF + (mt * 16 * A_ROWH + ks * 16) * 2);
#pragma unroll
            for (int ng = 0; ng < 4; ++ng) {
                uint32_t bb[4];
                LDSM4T(bb, bLd + buf * B_BUF + (ks * 16 * B_ROWH + ng * 16) * 2);
#pragma unroll
                for (int mt = 0; mt < 2; ++mt) {
                    MMA16816(d[mt][ng * 2 + 0], a[mt], bb[0], bb[1]);
                    MMA16816(d[mt][ng * 2 + 1], a[mt], bb[2], bb[3]);
                }
            }
        }
        if (++buf == 3) buf = 0;
    }

    const int r = ph >> 1, c = ph & 1;
#pragma unroll
    for (int mt = 0; mt < 2; ++mt) {
        int pxb = mtile * 128 + mwarp * 32 + mt * 16 + (lane >> 2);
#pragma unroll
        for (int rr = 0; rr < 2; ++rr) {
            int px = pxb + rr * 8;
            int Y = px / 66, X = px - Y * 66;
            if (X > 64 - c || Y > 64 - r) continue;
            __half2* ub = (__half2*)(g_u
                + (((size_t)(ph * 8 + b)) * NPU + (Y + 1) * 68 + (X + 1)) * COUT
                + cotile * 128);
#pragma unroll
            for (int nt = 0; nt < 8; ++nt) {
                int col = nwarp * 64 + nt * 8 + (lane & 3) * 2;
                ub[col >> 1] = __floats2half2_rn(d[mt][nt][rr * 2 + 0], d[mt][nt][rr * 2 + 1]);
            }
        }
    }
}

// ---------------------------------------------------------------------------
// blur: 4 output rows per CTA.  Same accumulation order as round-11 (passing);
// ONLY change: the 44 distinct su cells a thread touches per row l are hoisted
// into registers before the output loop (pure load hoisting — bit-identical).
// grid (32 t, 8 cochunk32, 8 b), 256 threads.
// ---------------------------------------------------------------------------
#define SROW   17
#define SPLANE (66 * SROW)
#define BLUR_SMEM (16 * SPLANE * 4)     // 71808 B

__global__ void __launch_bounds__(256, 3) k_blur(float* __restrict__ out) {
    extern __shared__ __align__(16) __half2 su[];
    const int tid = threadIdx.x;
    const int t = blockIdx.x, cochunk = blockIdx.y, b = blockIdx.z;
    const int cobase = cochunk * 32;
    const int co2 = tid & 15, oxg = tid >> 4;

    // load 4 planes x 4 rows (2t..2t+3) x 66 X x 16 half2
    for (int it = 0; it < 66; ++it) {
        int e = tid + it * 256;
        int cc = e & 15, rest = e >> 4;
        int X = rest % 66, pr = rest / 66;       // pr = plane*4+dr
        const __half2* src = (const __half2*)(g_u
            + (((size_t)((pr >> 2) * 8 + b)) * NPU + (size_t)(2 * t + (pr & 3)) * 68 + X) * COUT
            + cobase) + cc;
        su[(size_t)pr * SPLANE + X * SROW + cc] = *src;
    }
    __syncthreads();

    const float kv[4] = {0.25f, 0.75f, 0.75f, 0.25f};
    const int co = cobase + co2 * 2;
    const float dm0 = g_demod[b * 256 + co];
    const float dm1 = g_demod[b * 256 + co + 1];
    const int M4 = oxg * 4;

#pragma unroll
    for (int l = 0; l < 4; ++l) {
        const int u0 = 4 * t + l - 1;
        const int r0 = u0 & 1;
        int lrow[2][2]; float kva[2][2];
#pragma unroll
        for (int p = 0; p < 2; ++p) {
            int a0 = (p == r0) ? 0 : 1;
#pragma unroll
            for (int s = 0; s < 2; ++s) {
                lrow[p][s] = ((u0 + a0) >> 1) + s + 1 - 2 * t;   // 0..3
                kva[p][s] = kv[a0 + 2 * s];
            }
        }

        // hoisted loads: C0[ps][k-1] = plane(p*2+0) X=M4+k (k=1..5)
        //                C1[ps][k]   = plane(p*2+1) X=M4+k (k=0..5)
        __half2 C0[4][5], C1[4][6];
#pragma unroll
        for (int p = 0; p < 2; ++p)
#pragma unroll
            for (int s = 0; s < 2; ++s) {
                int ps = p * 2 + s;
                const __half2* r0p = su + (size_t)((p * 2 + 0) * 4 + lrow[p][s]) * SPLANE + co2;
                const __half2* r1p = su + (size_t)((p * 2 + 1) * 4 + lrow[p][s]) * SPLANE + co2;
#pragma unroll
                for (int k = 0; k < 6; ++k) {
                    C1[ps][k] = r1p[(M4 + k) * SROW];
                    if (k >= 1) C0[ps][k - 1] = r0p[(M4 + k) * SROW];
                }
            }

        float ax[8], ay[8];
#pragma unroll
        for (int i = 0; i < 8; ++i) {
            const int m = i >> 1;
            const int odd = i & 1;
            float sx = 0.f, sy = 0.f;
            // cp = 0: original b0 = odd?0:1, Xb+tt -> C0 idx m+tt (both parities)
#pragma unroll
            for (int tt = 0; tt < 2; ++tt) {
                float kvb = odd ? kv[2 * tt] : kv[1 + 2 * tt];
#pragma unroll
                for (int p = 0; p < 2; ++p)
#pragma unroll
                    for (int s = 0; s < 2; ++s) {
                        float w = kva[p][s] * kvb;
                        float2 vf = __half22float2(C0[p * 2 + s][m + tt]);
                        sx += w * vf.x; sy += w * vf.y;
                    }
            }
            // cp = 1: original b0 = odd?1:0, C1 idx = (odd ? m+1 : m) + tt
#pragma unroll
            for (int tt = 0; tt < 2; ++tt) {
                float kvb = odd ? kv[1 + 2 * tt] : kv[2 * tt];
                const int idx = (odd ? m + 1 : m) + tt;
#pragma unroll
                for (int p = 0; p < 2; ++p)
#pragma unroll
                    for (int s = 0; s < 2; ++s) {
                        float w = kva[p][s] * kvb;
                        float2 vf = __half22float2(C1[p * 2 + s][idx]);
                        sx += w * vf.x; sy += w * vf.y;
                    }
            }
            ax[i] = sx * dm0;
            ay[i] = sy * dm1;
        }
        const int oy = 4 * t + l;
        float* ob0 = out + (((size_t)b * 256 + co) * 128 + oy) * 128 + oxg * 8;
        float* ob1 = ob0 + 16384;
        ((float4*)ob0)[0] = make_float4(ax[0], ax[1], ax[2], ax[3]);
        ((float4*)ob0)[1] = make_float4(ax[4], ax[5], ax[6], ax[7]);
        ((float4*)ob1)[0] = make_float4(ay[0], ay[1], ay[2], ay[3]);
        ((float4*)ob1)[1] = make_float4(ay[4], ay[5], ay[6], ay[7]);
    }
}

// ---------------------------------------------------------------------------
extern "C" void kernel_launch(void* const* d_in, const int* in_sizes, int n_in,
                              void* d_out, int out_size) {
    const float* x          = (const float*)d_in[0];
    const float* style      = (const float*)d_in[1];
    const float* weight     = (const float*)d_in[2];
    const float* mod_weight = (const float*)d_in[3];
    const float* mod_bias   = (const float*)d_in[4];
    float* out = (float*)d_out;

    static int smem_set = 0;
    if (!smem_set) {
        cudaFuncSetAttribute(k_conv1, cudaFuncAttributeMaxDynamicSharedMemorySize, SMEM_DYN);
        cudaFuncSetAttribute(k_blur, cudaFuncAttributeMaxDynamicSharedMemorySize, BLUR_SMEM);
        smem_set = 1;
    }

    k_prep1<<<1104, 256>>>(style, mod_weight, mod_bias, weight);
    k_prep2<<<dim3(64, 9, 8), 256>>>(x);
    k_conv1<<<dim3(34, 2, 32), 256, SMEM_DYN>>>();
    k_blur<<<dim3(32, 8, 8), 256, BLUR_SMEM>>>(out);
}

// round 17
// speedup vs baseline: 1.1254x; 1.0660x over previous
#include <cuda_runtime.h>
#include <cuda_fp16.h>
#include <math.h>
#include <cstdint>

#define CIN   512
#define COUT  256
#define SDIM  512
#define NPS   4480          // per-batch padded pixel stride for Xt (66*66=4356 + slack)
#define NPU   4624          // 68*68 u-grid per (ph,b) plane

// ---------------- device scratch ----------------
__device__ float g_s[8 * CIN];
__device__ float g_wsq[COUT * CIN];
__device__ float g_demod[8 * COUT];
__device__ __align__(16) __half g_xt[(size_t)8 * NPS * CIN];         // 36.7 MB
__device__ __align__(16) __half g_wh[(size_t)9 * CIN * COUT];        // 2.36 MB
__device__ __align__(16) __half g_u[(size_t)4 * 8 * NPU * COUT];     // 75.8 MB

// convT phase taps: gt 0..8  (ph0:4, ph1:2, ph2:2, ph3:1)
__constant__ int c_tapd[9] = {0, 1, 66, 67, 1, 67, 66, 67, 67};
__constant__ int c_wsel[9] = {2*3+2, 2*3+0, 0*3+2, 0*3+0, 2*3+1, 0*3+1, 1*3+2, 1*3+0, 1*3+1};
__constant__ int c_toff[4] = {0, 4, 6, 8};
__constant__ int c_nit[4]  = {64, 32, 32, 16};

// ---------------- PTX helpers ----------------
__device__ __forceinline__ uint32_t smem_u32(const void* p) {
    uint32_t a;
    asm("{ .reg .u64 t; cvta.to.shared.u64 t, %1; cvt.u32.u64 %0, t; }" : "=r"(a) : "l"(p));
    return a;
}
__device__ __forceinline__ void cp16(uint32_t dst, const void* src) {
    asm volatile("cp.async.cg.shared.global [%0], [%1], 16;" :: "r"(dst), "l"(src));
}
#define CP_COMMIT() asm volatile("cp.async.commit_group;" ::: "memory")
#define CP_WAIT(n)  asm volatile("cp.async.wait_group %0;" :: "n"(n) : "memory")

#define LDSM4(r, a) asm volatile( \
    "ldmatrix.sync.aligned.m8n8.x4.shared.b16 {%0,%1,%2,%3},[%4];" \
    : "=r"((r)[0]),"=r"((r)[1]),"=r"((r)[2]),"=r"((r)[3]) : "r"(a))
#define LDSM4T(r, a) asm volatile( \
    "ldmatrix.sync.aligned.m8n8.x4.trans.shared.b16 {%0,%1,%2,%3},[%4];" \
    : "=r"((r)[0]),"=r"((r)[1]),"=r"((r)[2]),"=r"((r)[3]) : "r"(a))
#define MMA16816(d, a, b0, b1) asm volatile( \
    "mma.sync.aligned.m16n8k16.row.col.f32.f16.f16.f32 " \
    "{%0,%1,%2,%3},{%4,%5,%6,%7},{%8,%9},{%0,%1,%2,%3};" \
    : "+f"((d)[0]),"+f"((d)[1]),"+f"((d)[2]),"+f"((d)[3]) \
    : "r"((a)[0]),"r"((a)[1]),"r"((a)[2]),"r"((a)[3]), "r"(b0),"r"(b1))

// ---------------------------------------------------------------------------
// prep1: style (blocks 0..511) | wprep (512..1023) | zero_xtb (1024..1071)
//        | zero_ub (1072..1103).  All mutually independent.
// ---------------------------------------------------------------------------
__global__ void k_prep1(const float* __restrict__ style, const float* __restrict__ mw,
                        const float* __restrict__ mb, const float* __restrict__ weight) {
    const int bx = blockIdx.x, tid = threadIdx.x;
    if (bx < 512) {
        int idx = bx * 8 + (tid >> 5);
        int lane = tid & 31;
        int b = idx / CIN, ci = idx - b * CIN;
        const float* st = style + b * SDIM;
        const float* w = mw + ci * SDIM;
        float acc = 0.f;
        for (int d = lane; d < SDIM; d += 32) acc += st[d] * w[d];
#pragma unroll
        for (int o = 16; o; o >>= 1) acc += __shfl_xor_sync(0xffffffffu, acc, o);
        if (lane == 0) g_s[idx] = acc * 0.044194173824159216f + mb[ci];
    } else if (bx < 1024) {
        int idx = (bx - 512) * 256 + tid;
        int co = idx & 255, ci = idx >> 8;
        float w[9];
        float q = 0.f;
#pragma unroll
        for (int p = 0; p < 9; ++p) {
            w[p] = weight[((size_t)co * CIN + ci) * 9 + p];
            q += w[p] * w[p];
        }
        g_wsq[co * CIN + ci] = q;
#pragma unroll
        for (int gt = 0; gt < 9; ++gt)
            g_wh[((size_t)gt * CIN + ci) * COUT + co] = __float2half(w[c_wsel[gt]]);
    } else if (bx < 1072) {
        int c = bx - 1024;
        int row0 = (c % 6) * 64;
        __half* base = g_xt + (size_t)(c / 6) * NPS * CIN;
        for (int wk = tid; wk < 64 * 64; wk += 256) {
            int row = row0 + (wk >> 6), seg = wk & 63;
            int pp;
            if (row < 66)       pp = row;
            else if (row < 132) pp = 4290 + (row - 66);
            else if (row < 196) pp = (row - 131) * 66;
            else if (row < 260) pp = (row - 195) * 66 + 65;
            else                pp = 4356 + (row - 260);
            ((uint4*)(base + (size_t)pp * CIN))[seg] = make_uint4(0, 0, 0, 0);
        }
    } else {
        __half* base = g_u + (size_t)(bx - 1072) * NPU * COUT;
        for (int cell = tid >> 5; cell < 264; cell += 8) {
            int r, X;
            if (cell < 68)       { r = 0;          X = cell; }
            else if (cell < 136) { r = 65;         X = cell - 68; }
            else if (cell < 200) { r = cell - 135; X = 0; }
            else                 { r = cell - 199; X = 65; }
            uint4* p = (uint4*)(base + ((size_t)r * 68 + X) * COUT) + (tid & 31);
            *p = make_uint4(0, 0, 0, 0);
        }
    }
}

// ---------------------------------------------------------------------------
// prep2: xt transpose (blockIdx.y<8) | demod (blockIdx.y==8, blockIdx.x<32)
// grid (64, 9, 8)
// ---------------------------------------------------------------------------
__global__ void k_prep2(const float* __restrict__ x) {
    __shared__ float xs[64][65];
    __shared__ float ss[64];
    const int tid = threadIdx.x;
    if (blockIdx.y < 8) {
        int y = blockIdx.x, ch = blockIdx.y, b = blockIdx.z;
        int ci0 = ch * 64;
        if (tid < 64) ss[tid] = g_s[b * CIN + ci0 + tid];
#pragma unroll
        for (int t = 0; t < 16; ++t) {
            int e = tid + t * 256;
            int ci = e >> 6, xx = e & 63;
            xs[ci][xx] = x[(((size_t)b * CIN + ci0 + ci) * 64 + y) * 64 + xx];
        }
        __syncthreads();
#pragma unroll
        for (int t = 0; t < 4; ++t) {
            int g = tid + t * 256;
            int xx = g >> 4, gl = g & 15;
            __half2 h0 = __floats2half2_rn(xs[gl*4+0][xx] * ss[gl*4+0], xs[gl*4+1][xx] * ss[gl*4+1]);
            __half2 h1 = __floats2half2_rn(xs[gl*4+2][xx] * ss[gl*4+2], xs[gl*4+3][xx] * ss[gl*4+3]);
            size_t pp = (size_t)(y + 1) * 66 + (xx + 1);
            __half2* d = (__half2*)(g_xt + ((size_t)b * NPS + pp) * CIN + ci0 + gl * 4);
            d[0] = h0; d[1] = h1;
        }
    } else if (blockIdx.x < 32) {
        int idx = (blockIdx.x * 8 + blockIdx.z) * 8 + (tid >> 5);
        int lane = tid & 31;
        int b = idx / COUT, co = idx - b * COUT;
        float acc = 0.f;
        for (int ci = lane; ci < CIN; ci += 32) {
            float sv = g_s[b * CIN + ci];
            acc += sv * sv * g_wsq[co * CIN + ci];
        }
#pragma unroll
        for (int o = 16; o; o >>= 1) acc += __shfl_xor_sync(0xffffffffu, acc, o);
        if (lane == 0)
            g_demod[idx] = 0.014731391274719738f * rsqrtf(2.1701388888888888e-4f * acc + 1e-8f);
    }
}

// ---------------------------------------------------------------------------
// convT phase GEMM (unchanged): CTA = 128px x 128co, 8 warps, 32x64 tiles.
// grid: (34 mtiles, 2 cotiles, 32 = ph*8+b) — ph0 (longest CTAs) first.
// ---------------------------------------------------------------------------
#define A_ROWH   40
#define B_ROWH   136
#define A_BUF    (128 * A_ROWH * 2)
#define B_BUF    (32 * B_ROWH * 2)
#define SMEM_DYN (3 * (A_BUF + B_BUF))

__global__ void __launch_bounds__(256, 2) k_conv1() {
    extern __shared__ __align__(16) char smem[];
    __half* Asm = (__half*)smem;
    __half* Bsm = (__half*)(smem + 3 * A_BUF);

    const int tid = threadIdx.x, lane = tid & 31, wid = tid >> 5;
    const int mtile = blockIdx.x, cotile = blockIdx.y;
    const int ph = blockIdx.z >> 3, b = blockIdx.z & 7;
    const int toff = c_toff[ph], NITER = c_nit[ph];
    const int mwarp = wid & 3, nwarp = wid >> 2;

    const int arow = tid >> 1;
    const int apx = mtile * 128 + arow;
    const __half* aSrc = g_xt + ((size_t)b * NPS + apx) * CIN + (tid & 1) * 16;
    const uint32_t aDst = smem_u32(Asm) + (arow * A_ROWH + (tid & 1) * 16) * 2;

    const __half* bSrc = g_wh + (size_t)(tid >> 3) * COUT + cotile * 128 + (tid & 7) * 8;
    const uint32_t bDst = smem_u32(Bsm) + ((tid >> 3) * B_ROWH + (tid & 7) * 8) * 2;

    const uint32_t aLd = smem_u32(Asm)
        + (((lane & 7) + ((lane >> 3) & 1) * 8 + mwarp * 32) * A_ROWH + (lane >> 4) * 8) * 2;
    const uint32_t bLd = smem_u32(Bsm)
        + ((((lane >> 3) & 1) * 8 + (lane & 7)) * B_ROWH + (lane >> 4) * 8 + nwarp * 64) * 2;

    float d[2][8][4];
#pragma unroll
    for (int i = 0; i < 2; ++i)
#pragma unroll
        for (int j = 0; j < 8; ++j)
#pragma unroll
            for (int k = 0; k < 4; ++k) d[i][j][k] = 0.f;

    auto load = [&](int j, int buf) {
        int gt = toff + (j >> 4), cic = j & 15;
        const __half* as = aSrc + ((ptrdiff_t)c_tapd[gt] << 9) + cic * 32;
        uint32_t ad = aDst + buf * A_BUF;
        cp16(ad, as);
        cp16(ad + 16, as + 8);
        const __half* bs = bSrc + ((size_t)gt * CIN + cic * 32) * COUT;
        uint32_t bd = bDst + buf * B_BUF;
        cp16(bd, bs);
        cp16(bd + 128, bs + 64);
    };

    load(0, 0); CP_COMMIT();
    load(1, 1); CP_COMMIT();

    int buf = 0;
    for (int j = 0; j < NITER; ++j) {
        CP_WAIT(1);
        __syncthreads();
        if (j < NITER - 2) {
            int nbuf = buf + 2; if (nbuf >= 3) nbuf -= 3;
            load(j + 2, nbuf);
            CP_COMMIT();
        }
#pragma unroll
        for (int ks = 0; ks < 2; ++ks) {
            uint32_t a[2][4];
#pragma unroll
            for (int mt = 0; mt < 2; ++mt)
                LDSM4(a[mt], aLd + buf * A_BUF + (mt * 16 * A_ROWH + ks * 16) * 2);
#pragma unroll
            for (int ng = 0; ng < 4; ++ng) {
                uint32_t bb[4];
                LDSM4T(bb, bLd + buf * B_BUF + (ks * 16 * B_ROWH + ng * 16) * 2);
#pragma unroll
                for (int mt = 0; mt < 2; ++mt) {
                    MMA16816(d[mt][ng * 2 + 0], a[mt], bb[0], bb[1]);
                    MMA16816(d[mt][ng * 2 + 1], a[mt], bb[2], bb[3]);
                }
            }
        }
        if (++buf == 3) buf = 0;
    }

    const int r = ph >> 1, c = ph & 1;
#pragma unroll
    for (int mt = 0; mt < 2; ++mt) {
        int pxb = mtile * 128 + mwarp * 32 + mt * 16 + (lane >> 2);
#pragma unroll
        for (int rr = 0; rr < 2; ++rr) {
            int px = pxb + rr * 8;
            int Y = px / 66, X = px - Y * 66;
            if (X > 64 - c || Y > 64 - r) continue;
            __half2* ub = (__half2*)(g_u
                + (((size_t)(ph * 8 + b)) * NPU + (Y + 1) * 68 + (X + 1)) * COUT
                + cotile * 128);
#pragma unroll
            for (int nt = 0; nt < 8; ++nt) {
                int col = nwarp * 64 + nt * 8 + (lane & 3) * 2;
                ub[col >> 1] = __floats2half2_rn(d[mt][nt][rr * 2 + 0], d[mt][nt][rr * 2 + 1]);
            }
        }
    }
}

// ---------------------------------------------------------------------------
// blur: 4 output rows per CTA; round-11 accumulation order (bit-identical).
// Loader: cp.async 16B — SROW=16 so every su cell (64 B) is 16B-aligned.
// grid (32 t, 8 cochunk32, 8 b), 256 threads, 3 CTAs/SM.
// ---------------------------------------------------------------------------
#define SROW   16
#define SPLANE (66 * SROW)
#define BLUR_SMEM (16 * SPLANE * 4)     // 67584 B

__global__ void __launch_bounds__(256, 3) k_blur(float* __restrict__ out) {
    extern __shared__ __align__(16) __half2 su[];
    const int tid = threadIdx.x;
    const int t = blockIdx.x, cochunk = blockIdx.y, b = blockIdx.z;
    const int cobase = cochunk * 32;
    const int co2 = tid & 15, oxg = tid >> 4;

    // cp.async loader: 16 plane-rows x 66 X cells, 64 B each = 4224 cp16 ops
    {
        const uint32_t subase = smem_u32(su);
        for (int e = tid; e < 4224; e += 256) {
            int q = e & 3;              // 16B quarter within the 64B co-row
            int rx = e >> 2;            // pr*66 + X
            int X = rx % 66, pr = rx / 66;
            const __half* src = g_u
                + (((size_t)((pr >> 2) * 8 + b)) * NPU + (size_t)(2 * t + (pr & 3)) * 68 + X) * COUT
                + cobase + q * 8;
            cp16(subase + ((uint32_t)pr * SPLANE + X * SROW) * 4 + q * 16, src);
        }
        CP_COMMIT();
        CP_WAIT(0);
    }
    __syncthreads();

    const float kv[4] = {0.25f, 0.75f, 0.75f, 0.25f};
    const int co = cobase + co2 * 2;
    const float dm0 = g_demod[b * 256 + co];
    const float dm1 = g_demod[b * 256 + co + 1];
    const int M4 = oxg * 4;

#pragma unroll
    for (int l = 0; l < 4; ++l) {
        const int u0 = 4 * t + l - 1;
        const int r0 = u0 & 1;
        int lrow[2][2]; float kva[2][2];
#pragma unroll
        for (int p = 0; p < 2; ++p) {
            int a0 = (p == r0) ? 0 : 1;
#pragma unroll
            for (int s = 0; s < 2; ++s) {
                lrow[p][s] = ((u0 + a0) >> 1) + s + 1 - 2 * t;   // 0..3
                kva[p][s] = kv[a0 + 2 * s];
            }
        }

        // hoisted loads: C0[ps][k-1] = plane(p*2+0) X=M4+k (k=1..5)
        //                C1[ps][k]   = plane(p*2+1) X=M4+k (k=0..5)
        __half2 C0[4][5], C1[4][6];
#pragma unroll
        for (int p = 0; p < 2; ++p)
#pragma unroll
            for (int s = 0; s < 2; ++s) {
                int ps = p * 2 + s;
                const __half2* r0p = su + (size_t)((p * 2 + 0) * 4 + lrow[p][s]) * SPLANE + co2;
                const __half2* r1p = su + (size_t)((p * 2 + 1) * 4 + lrow[p][s]) * SPLANE + co2;
#pragma unroll
                for (int k = 0; k < 6; ++k) {
                    C1[ps][k] = r1p[(M4 + k) * SROW];
                    if (k >= 1) C0[ps][k - 1] = r0p[(M4 + k) * SROW];
                }
            }

        float ax[8], ay[8];
#pragma unroll
        for (int i = 0; i < 8; ++i) {
            const int m = i >> 1;
            const int odd = i & 1;
            float sx = 0.f, sy = 0.f;
#pragma unroll
            for (int tt = 0; tt < 2; ++tt) {
                float kvb = odd ? kv[2 * tt] : kv[1 + 2 * tt];
#pragma unroll
                for (int p = 0; p < 2; ++p)
#pragma unroll
                    for (int s = 0; s < 2; ++s) {
                        float w = kva[p][s] * kvb;
                        float2 vf = __half22float2(C0[p * 2 + s][m + tt]);
                        sx += w * vf.x; sy += w * vf.y;
                    }
            }
#pragma unroll
            for (int tt = 0; tt < 2; ++tt) {
                float kvb = odd ? kv[1 + 2 * tt] : kv[2 * tt];
                const int idx = (odd ? m + 1 : m) + tt;
#pragma unroll
                for (int p = 0; p < 2; ++p)
#pragma unroll
                    for (int s = 0; s < 2; ++s) {
                        float w = kva[p][s] * kvb;
                        float2 vf = __half22float2(C1[p * 2 + s][idx]);
                        sx += w * vf.x; sy += w * vf.y;
                    }
            }
            ax[i] = sx * dm0;
            ay[i] = sy * dm1;
        }
        const int oy = 4 * t + l;
        float* ob0 = out + (((size_t)b * 256 + co) * 128 + oy) * 128 + oxg * 8;
        float* ob1 = ob0 + 16384;
        ((float4*)ob0)[0] = make_float4(ax[0], ax[1], ax[2], ax[3]);
        ((float4*)ob0)[1] = make_float4(ax[4], ax[5], ax[6], ax[7]);
        ((float4*)ob1)[0] = make_float4(ay[0], ay[1], ay[2], ay[3]);
        ((float4*)ob1)[1] = make_float4(ay[4], ay[5], ay[6], ay[7]);
    }
}

// ---------------------------------------------------------------------------
extern "C" void kernel_launch(void* const* d_in, const int* in_sizes, int n_in,
                              void* d_out, int out_size) {
    const float* x          = (const float*)d_in[0];
    const float* style      = (const float*)d_in[1];
    const float* weight     = (const float*)d_in[2];
    const float* mod_weight = (const float*)d_in[3];
    const float* mod_bias   = (const float*)d_in[4];
    float* out = (float*)d_out;

    static int smem_set = 0;
    if (!smem_set) {
        cudaFuncSetAttribute(k_conv1, cudaFuncAttributeMaxDynamicSharedMemorySize, SMEM_DYN);
        cudaFuncSetAttribute(k_blur, cudaFuncAttributeMaxDynamicSharedMemorySize, BLUR_SMEM);
        smem_set = 1;
    }

    k_prep1<<<1104, 256>>>(style, mod_weight, mod_bias, weight);
    k_prep2<<<dim3(64, 9, 8), 256>>>(x);
    k_conv1<<<dim3(34, 2, 32), 256, SMEM_DYN>>>();
    k_blur<<<dim3(32, 8, 8), 256, BLUR_SMEM>>>(out);
}